// round 1
// baseline (speedup 1.0000x reference)
#include <cuda_runtime.h>
#include <cuda_bf16.h>

// Problem constants
#define Bc 8
#define Cc 5
#define Hc 64
#define Wc 2048
#define Nc 1048576
#define Dc 64
#define Fc 4
#define HWc (Hc * Wc)                  // 131072

// Output section offsets (elements, float32 output, reference tuple order)
#define OFF_SCAN   0LL
#define OFF_COORD  5242880LL           // B*C*H*W
#define OFF_LABEL  11534336LL          // + 2N*3
#define OFF_EMBED  12582912LL          // + B*H*W
#define OFF_VALID  146800640LL         // + 2N*D

// ---------------------------------------------------------------------------
// Kernel A: mix_range_scan + mix_pred_label
// One thread per (b, h, w-quad). Evaluates the 4-rect box mask inline,
// selects source batch per element, writes float4 per channel + label.
// ---------------------------------------------------------------------------
__global__ __launch_bounds__(256) void mix_scan_label_kernel(
    const float* __restrict__ scan,
    const int*   __restrict__ label,
    const int*   __restrict__ u,
    const int*   __restrict__ bbw1, const int* __restrict__ bbw2,
    const int*   __restrict__ bbh1, const int* __restrict__ bbh2,
    float*       __restrict__ out)
{
    const int W4 = Wc / 4;
    int t = blockIdx.x * blockDim.x + threadIdx.x;     // 0 .. B*H*W4-1
    if (t >= Bc * Hc * W4) return;
    int w4 = t % W4;
    int h  = (t / W4) % Hc;
    int b  = t / (W4 * Hc);
    int w0 = w4 * 4;

    // box mask for the 4 consecutive w positions
    bool box0 = false, box1 = false, box2 = false, box3 = false;
#pragma unroll
    for (int f = 0; f < Fc; f++) {
        int h1 = __ldg(bbh1 + b * Fc + f);
        int h2 = __ldg(bbh2 + b * Fc + f);
        if (h >= h1 && h < h2) {
            int w1 = __ldg(bbw1 + b * Fc + f);
            int w2 = __ldg(bbw2 + b * Fc + f);
            box0 |= (w0 + 0 >= w1 && w0 + 0 < w2);
            box1 |= (w0 + 1 >= w1 && w0 + 1 < w2);
            box2 |= (w0 + 2 >= w1 && w0 + 2 < w2);
            box3 |= (w0 + 3 >= w1 && w0 + 3 < w2);
        }
    }
    int ub = __ldg(u + b);
    long long base = (long long)h * Wc + w0;

    // pred_label (int -> float)
    {
        const int* lb = label + (long long)b  * HWc + base;
        const int* lu = label + (long long)ub * HWc + base;
        float4 v;
        v.x = (float)(box0 ? __ldg(lu + 0) : __ldg(lb + 0));
        v.y = (float)(box1 ? __ldg(lu + 1) : __ldg(lb + 1));
        v.z = (float)(box2 ? __ldg(lu + 2) : __ldg(lb + 2));
        v.w = (float)(box3 ? __ldg(lu + 3) : __ldg(lb + 3));
        *(float4*)(out + OFF_LABEL + (long long)b * HWc + base) = v;
    }

    // range_scan, 5 channels
#pragma unroll
    for (int c = 0; c < Cc; c++) {
        const float* sb = scan + ((long long)b  * Cc + c) * HWc + base;
        const float* su = scan + ((long long)ub * Cc + c) * HWc + base;
        float4 v;
        v.x = box0 ? __ldg(su + 0) : __ldg(sb + 0);
        v.y = box1 ? __ldg(su + 1) : __ldg(sb + 1);
        v.z = box2 ? __ldg(su + 2) : __ldg(sb + 2);
        v.w = box3 ? __ldg(su + 3) : __ldg(sb + 3);
        *(float4*)(out + OFF_SCAN + ((long long)b * Cc + c) * HWc + base) = v;
    }
}

// ---------------------------------------------------------------------------
// Kernel B: mix_project_coord + mix_range_embed + valid
// 8 threads per point. Shared-staged bb arrays + u + inv_perm.
// Embed row read once per point, written (masked) to both output halves.
// ---------------------------------------------------------------------------
__device__ __forceinline__ bool box_eval(
    const int* s_h1, const int* s_h2, const int* s_w1, const int* s_w2,
    int b, int h, int w)
{
    bool r = false;
#pragma unroll
    for (int f = 0; f < Fc; f++) {
        int i = b * Fc + f;
        r |= (h >= s_h1[i]) & (h < s_h2[i]) & (w >= s_w1[i]) & (w < s_w2[i]);
    }
    return r;
}

__global__ __launch_bounds__(256) void mix_points_kernel(
    const int*   __restrict__ pc,
    const float* __restrict__ embed,
    const int*   __restrict__ u,
    const int*   __restrict__ bbw1, const int* __restrict__ bbw2,
    const int*   __restrict__ bbh1, const int* __restrict__ bbh2,
    float*       __restrict__ out)
{
    __shared__ int s_u[Bc], s_inv[Bc];
    __shared__ int s_h1[Bc * Fc], s_h2[Bc * Fc], s_w1[Bc * Fc], s_w2[Bc * Fc];

    int tid = threadIdx.x;
    if (tid < Bc * Fc) {
        s_h1[tid] = bbh1[tid];
        s_h2[tid] = bbh2[tid];
        s_w1[tid] = bbw1[tid];
        s_w2[tid] = bbw2[tid];
    }
    if (tid < Bc) s_u[tid] = u[tid];
    __syncthreads();
    if (tid < Bc) s_inv[s_u[tid]] = tid;
    __syncthreads();

    long long g = (long long)blockIdx.x * (blockDim.x / 8) + (tid >> 3);  // point id
    int l = tid & 7;
    if (g >= Nc) return;

    int pb = __ldg(pc + g * 3 + 0);
    int pw = __ldg(pc + g * 3 + 1);
    int ph = __ldg(pc + g * 3 + 2);
    int icut = s_inv[pb];

    bool own  = box_eval(s_h1, s_h2, s_w1, s_w2, pb,   ph, pw);
    bool cut  = box_eval(s_h1, s_h2, s_w1, s_w2, icut, ph, pw);
    bool keep = !own;

    // embed: read once, masked double-write
    const float4 z = make_float4(0.f, 0.f, 0.f, 0.f);
    float4 v0 = z, v1 = z;
    if (keep | cut) {
        const float4* src = (const float4*)(embed + g * 64) + l * 2;
        v0 = __ldg(src);
        v1 = __ldg(src + 1);
    }
    float4* o1 = (float4*)(out + OFF_EMBED + g * 64) + l * 2;
    float4* o2 = (float4*)(out + OFF_EMBED + ((long long)Nc + g) * 64) + l * 2;
    o1[0] = keep ? v0 : z;
    o1[1] = keep ? v1 : z;
    o2[0] = cut  ? v0 : z;
    o2[1] = cut  ? v1 : z;

    if (l == 0) {
        float* oc = out + OFF_COORD + g * 3;
        oc[0] = keep ? (float)pb : -1.f;
        oc[1] = keep ? (float)pw : -1.f;
        oc[2] = keep ? (float)ph : -1.f;
        out[OFF_VALID + g] = keep ? 1.f : 0.f;
    } else if (l == 1) {
        float* oc = out + OFF_COORD + ((long long)Nc + g) * 3;
        oc[0] = cut ? (float)icut : -1.f;
        oc[1] = cut ? (float)pw   : -1.f;
        oc[2] = cut ? (float)ph   : -1.f;
        out[OFF_VALID + (long long)Nc + g] = cut ? 1.f : 0.f;
    }
}

extern "C" void kernel_launch(void* const* d_in, const int* in_sizes, int n_in,
                              void* d_out, int out_size)
{
    const float* range_scan  = (const float*)d_in[0];
    const int*   pc          = (const int*)  d_in[1];
    const float* range_embed = (const float*)d_in[2];
    const int*   pred_label  = (const int*)  d_in[3];
    const int*   u_rand      = (const int*)  d_in[4];
    const int*   bbw1        = (const int*)  d_in[5];
    const int*   bbw2        = (const int*)  d_in[6];
    const int*   bbh1        = (const int*)  d_in[7];
    const int*   bbh2        = (const int*)  d_in[8];
    float* out = (float*)d_out;

    // Kernel A: B*H*(W/4) = 262144 threads
    {
        int total = Bc * Hc * (Wc / 4);
        int threads = 256;
        int blocks = (total + threads - 1) / threads;
        mix_scan_label_kernel<<<blocks, threads>>>(
            range_scan, pred_label, u_rand, bbw1, bbw2, bbh1, bbh2, out);
    }
    // Kernel B: N points * 8 threads each
    {
        long long total = (long long)Nc * 8;
        int threads = 256;
        long long blocks = (total + threads - 1) / threads;
        mix_points_kernel<<<(unsigned)blocks, threads>>>(
            pc, range_embed, u_rand, bbw1, bbw2, bbh1, bbh2, out);
    }
}

// round 2
// speedup vs baseline: 1.0469x; 1.0469x over previous
#include <cuda_runtime.h>
#include <cuda_bf16.h>

// Problem constants
#define Bc 8
#define Cc 5
#define Hc 64
#define Wc 2048
#define Nc 1048576
#define Dc 64
#define Fc 4
#define HWc (Hc * Wc)                  // 131072

// Output section offsets (float32 elements, reference tuple order)
#define OFF_SCAN   0LL
#define OFF_COORD  5242880LL           // B*C*H*W
#define OFF_LABEL  11534336LL          // + 2N*3
#define OFF_EMBED  12582912LL          // + B*H*W
#define OFF_VALID  146800640LL         // + 2N*D

// Grid split: A (scan/label) blocks first, then B (points) blocks.
#define A_TOTAL   (Bc * Hc * (Wc / 4))     // 131072 threads
#define A_BLOCKS  ((A_TOTAL + 255) / 256)  // 512
#define B_BLOCKS  (Nc / 32)                // 32768 (32 points per 256-thr block)

__device__ __forceinline__ bool box_eval(
    const int* s_h1, const int* s_h2, const int* s_w1, const int* s_w2,
    int b, int h, int w)
{
    bool r = false;
#pragma unroll
    for (int f = 0; f < Fc; f++) {
        int i = b * Fc + f;
        r |= (h >= s_h1[i]) & (h < s_h2[i]) & (w >= s_w1[i]) & (w < s_w2[i]);
    }
    return r;
}

__global__ __launch_bounds__(256) void range_mix_fused_kernel(
    const float* __restrict__ scan,
    const int*   __restrict__ pc,
    const float* __restrict__ embed,
    const int*   __restrict__ label,
    const int*   __restrict__ u,
    const int*   __restrict__ bbw1, const int* __restrict__ bbw2,
    const int*   __restrict__ bbh1, const int* __restrict__ bbh2,
    float*       __restrict__ out)
{
    const int tid = threadIdx.x;

    if (blockIdx.x < A_BLOCKS) {
        // ----------------- Part A: mix_range_scan + mix_pred_label -----------------
        int t = blockIdx.x * 256 + tid;
        if (t >= A_TOTAL) return;
        const int W4 = Wc / 4;
        int w4 = t % W4;
        int h  = (t / W4) % Hc;
        int b  = t / (W4 * Hc);
        int w0 = w4 * 4;

        bool box0 = false, box1 = false, box2 = false, box3 = false;
#pragma unroll
        for (int f = 0; f < Fc; f++) {
            int h1 = __ldg(bbh1 + b * Fc + f);
            int h2 = __ldg(bbh2 + b * Fc + f);
            if (h >= h1 && h < h2) {
                int w1 = __ldg(bbw1 + b * Fc + f);
                int w2 = __ldg(bbw2 + b * Fc + f);
                box0 |= (w0 + 0 >= w1 && w0 + 0 < w2);
                box1 |= (w0 + 1 >= w1 && w0 + 1 < w2);
                box2 |= (w0 + 2 >= w1 && w0 + 2 < w2);
                box3 |= (w0 + 3 >= w1 && w0 + 3 < w2);
            }
        }
        int ub = __ldg(u + b);
        long long base = (long long)h * Wc + w0;

        // pred_label (int -> float)
        {
            const int4 lb = __ldcs((const int4*)(label + (long long)b  * HWc + base));
            const int4 lu = (box0|box1|box2|box3)
                          ? __ldcs((const int4*)(label + (long long)ub * HWc + base))
                          : lb;
            float4 v;
            v.x = (float)(box0 ? lu.x : lb.x);
            v.y = (float)(box1 ? lu.y : lb.y);
            v.z = (float)(box2 ? lu.z : lb.z);
            v.w = (float)(box3 ? lu.w : lb.w);
            __stcs((float4*)(out + OFF_LABEL + (long long)b * HWc + base), v);
        }
        // range_scan, 5 channels
#pragma unroll
        for (int c = 0; c < Cc; c++) {
            const float4 sb = __ldcs((const float4*)(scan + ((long long)b  * Cc + c) * HWc + base));
            const float4 su = (box0|box1|box2|box3)
                            ? __ldcs((const float4*)(scan + ((long long)ub * Cc + c) * HWc + base))
                            : sb;
            float4 v;
            v.x = box0 ? su.x : sb.x;
            v.y = box1 ? su.y : sb.y;
            v.z = box2 ? su.z : sb.z;
            v.w = box3 ? su.w : sb.w;
            __stcs((float4*)(out + OFF_SCAN + ((long long)b * Cc + c) * HWc + base), v);
        }
        return;
    }

    // ----------------- Part B: coords + embed + valid -----------------
    __shared__ int s_u[Bc], s_inv[Bc];
    __shared__ int s_h1[Bc * Fc], s_h2[Bc * Fc], s_w1[Bc * Fc], s_w2[Bc * Fc];

    if (tid < Bc * Fc) {
        s_h1[tid] = bbh1[tid];
        s_h2[tid] = bbh2[tid];
        s_w1[tid] = bbw1[tid];
        s_w2[tid] = bbw2[tid];
    }
    if (tid < Bc) s_u[tid] = u[tid];
    __syncthreads();
    if (tid < Bc) s_inv[s_u[tid]] = tid;
    __syncthreads();

    long long g = (long long)(blockIdx.x - A_BLOCKS) * 32 + (tid >> 3);  // point id
    int l = tid & 3;            // float4 index within 128B half
    int half = (tid >> 2) & 1;  // not used; recompute below
    (void)half;
    l = tid & 7;                // 8 lanes per point, lane l covers float4 l and l+8

    int pb = __ldg(pc + g * 3 + 0);
    int pw = __ldg(pc + g * 3 + 1);
    int ph = __ldg(pc + g * 3 + 2);
    int icut = s_inv[pb];

    bool own  = box_eval(s_h1, s_h2, s_w1, s_w2, pb,   ph, pw);
    bool cut  = box_eval(s_h1, s_h2, s_w1, s_w2, icut, ph, pw);
    bool keep = !own;

    // embed row: lane l loads float4 #l and #(l+8) -> warp requests are
    // fully contiguous 128B segments (full sectors per instruction).
    const float4 z = make_float4(0.f, 0.f, 0.f, 0.f);
    float4 v0 = z, v1 = z;
    if (keep | cut) {
        const float4* src = (const float4*)(embed + g * 64);
        v0 = __ldcs(src + l);
        v1 = __ldcs(src + l + 8);
    }
    float4* o1 = (float4*)(out + OFF_EMBED + g * 64);
    float4* o2 = (float4*)(out + OFF_EMBED + ((long long)Nc + g) * 64);
    __stcs(o1 + l,     keep ? v0 : z);
    __stcs(o1 + l + 8, keep ? v1 : z);
    __stcs(o2 + l,     cut  ? v0 : z);
    __stcs(o2 + l + 8, cut  ? v1 : z);

    if (l == 0) {
        float* oc = out + OFF_COORD + g * 3;
        oc[0] = keep ? (float)pb : -1.f;
        oc[1] = keep ? (float)pw : -1.f;
        oc[2] = keep ? (float)ph : -1.f;
        out[OFF_VALID + g] = keep ? 1.f : 0.f;
    } else if (l == 1) {
        float* oc = out + OFF_COORD + ((long long)Nc + g) * 3;
        oc[0] = cut ? (float)icut : -1.f;
        oc[1] = cut ? (float)pw   : -1.f;
        oc[2] = cut ? (float)ph   : -1.f;
        out[OFF_VALID + (long long)Nc + g] = cut ? 1.f : 0.f;
    }
}

extern "C" void kernel_launch(void* const* d_in, const int* in_sizes, int n_in,
                              void* d_out, int out_size)
{
    const float* range_scan  = (const float*)d_in[0];
    const int*   pc          = (const int*)  d_in[1];
    const float* range_embed = (const float*)d_in[2];
    const int*   pred_label  = (const int*)  d_in[3];
    const int*   u_rand      = (const int*)  d_in[4];
    const int*   bbw1        = (const int*)  d_in[5];
    const int*   bbw2        = (const int*)  d_in[6];
    const int*   bbh1        = (const int*)  d_in[7];
    const int*   bbh2        = (const int*)  d_in[8];
    float* out = (float*)d_out;

    range_mix_fused_kernel<<<A_BLOCKS + B_BLOCKS, 256>>>(
        range_scan, pc, range_embed, pred_label, u_rand,
        bbw1, bbw2, bbh1, bbh2, out);
}